// round 14
// baseline (speedup 1.0000x reference)
#include <cuda_runtime.h>
#include <cuda_fp16.h>
#include <math.h>
#include <stdint.h>

// Problem constants
#define B_    16
#define C_    1024
#define T_    64
#define N_    12
#define BT_   (B_ * T_)       // 1024 frames
#define NF_   1024
#define ROWS_ (BT_ * N_)      // 12288
#define TN_   (T_ * N_)       // 768
#define NB_   2048            // fused B rows: [MwT | wg^T]

// Scratch (static device globals)
__device__ __half g_feat[ROWS_ * NF_];   // feat, rn-rounded to fp16
__device__ __half g_TG[ROWS_ * NB_];     // [tM | G] fused output (fp16)
__device__ __half g_BigB[NB_ * NF_];     // rows 0-1023: MwT, 1024-2047: wg^T
__device__ __half g_wtr[NF_ * NF_];      // Wtheta rounded to fp16
__device__ __half g_wpr[NF_ * NF_];      // Wphi rounded to fp16
__device__ float  g_vtp[NF_];
__device__ float  g_vpt[NF_];
__device__ float  g_bb[1];
__device__ float  g_rg[BT_ * N_ * N_];   // relation graph scratch

// ---------------------------------------------------------------------------
// Helpers (baseline PTX only)
// ---------------------------------------------------------------------------
__device__ __forceinline__ uint32_t smem_u32(const void* p) {
    uint32_t a;
    asm("{ .reg .u64 t; cvta.to.shared.u64 t, %1; cvt.u32.u64 %0, t; }" : "=r"(a) : "l"(p));
    return a;
}
__device__ __forceinline__ void cp16(uint32_t s, const void* g) {
    asm volatile("cp.async.cg.shared.global [%0], [%1], 16;" :: "r"(s), "l"(g) : "memory");
}
#define CP_COMMIT() asm volatile("cp.async.commit_group;" ::: "memory")
#define SWZ(x) ((x) ^ (((x) >> 3) & 0x70))

__device__ __forceinline__ void ldsm4(uint32_t* r, uint32_t addr) {
    asm volatile("ldmatrix.sync.aligned.m8n8.x4.shared.b16 {%0,%1,%2,%3}, [%4];"
                 : "=r"(r[0]), "=r"(r[1]), "=r"(r[2]), "=r"(r[3]) : "r"(addr));
}
// fp16 MMA, fp32 accumulate
__device__ __forceinline__ void mma_f16(float* c, const uint32_t* a, uint32_t b0, uint32_t b1) {
    asm volatile("mma.sync.aligned.m16n8k16.row.col.f32.f16.f16.f32 "
                 "{%0,%1,%2,%3}, {%4,%5,%6,%7}, {%8,%9}, {%0,%1,%2,%3};"
                 : "+f"(c[0]), "+f"(c[1]), "+f"(c[2]), "+f"(c[3])
                 : "r"(a[0]), "r"(a[1]), "r"(a[2]), "r"(a[3]), "r"(b0), "r"(b1));
}

#define BK 64          // fp16: 64 halves = 128B rows
#define STAGES 3

// ---------------------------------------------------------------------------
// Big GEMM (fp16): 128 thr (4 warps), CTA 128x128, warp 64x64, 3 stages,
// 2 CTA/SM. C[m,n] = sum_k A[m,k]*Bm[n,k]; half in, half out.
// ---------------------------------------------------------------------------
#define BIG_STG 16384
#define BIG_SMEM (STAGES * 2 * BIG_STG)   // 98304

__global__ void __launch_bounds__(128, 2) mma_gemm_big(const __half* __restrict__ A,
                                                       const __half* __restrict__ Bm,
                                                       __half* __restrict__ C) {
    const int K = NF_, ldc = NB_;
    extern __shared__ char smem[];
    const uint32_t sb = smem_u32(smem);
    const int tid = threadIdx.x, lane = tid & 31, wid = tid >> 5;
    const int m0 = blockIdx.y * 128, n0 = blockIdx.x * 128;
    const int warp_m = wid & 1, warp_n = wid >> 1;   // 2x2 warps, 64x64 each

    const int r = tid >> 3;
    const int o16 = (tid & 7) << 4;
    const int c8 = (tid & 7) << 3;

    float acc[4][8][4];
#pragma unroll
    for (int i = 0; i < 4; i++)
#pragma unroll
        for (int j = 0; j < 8; j++)
#pragma unroll
            for (int k = 0; k < 4; k++) acc[i][j][k] = 0.f;

    const int lrow = lane & 15;
    const int lcol = (lane >> 4) << 4;
    uint32_t a_base[4], b_base[4];
#pragma unroll
    for (int mt = 0; mt < 4; mt++)
        a_base[mt] = (uint32_t)((warp_m * 64 + mt * 16 + lrow) * 128 + lcol);
#pragma unroll
    for (int nh = 0; nh < 4; nh++)
        b_base[nh] = (uint32_t)((warp_n * 64 + nh * 16 + lrow) * 128 + lcol);

#define LOAD_STAGE_BIG(chunk, stage)                                               \
    do {                                                                           \
        uint32_t sA = sb + (stage) * BIG_STG;                                      \
        uint32_t sB = sb + STAGES * BIG_STG + (stage) * BIG_STG;                   \
        int k0 = (chunk) * BK;                                                     \
        _Pragma("unroll") for (int t = 0; t < 8; t++) {                            \
            int rr = r + t * 16;                                                   \
            cp16(sA + SWZ((uint32_t)(rr * 128 + o16)),                             \
                 A + (size_t)(m0 + rr) * K + k0 + c8);                             \
        }                                                                          \
        _Pragma("unroll") for (int t = 0; t < 8; t++) {                            \
            int rr = r + t * 16;                                                   \
            cp16(sB + SWZ((uint32_t)(rr * 128 + o16)),                             \
                 Bm + (size_t)(n0 + rr) * K + k0 + c8);                            \
        }                                                                          \
        CP_COMMIT();                                                               \
    } while (0)

    LOAD_STAGE_BIG(0, 0);
    LOAD_STAGE_BIG(1, 1);

    const int nk = K / BK;  // 16
    for (int i = 0; i < nk; i++) {
        const int st = i % STAGES;
        if (i + 2 < nk) {
            asm volatile("cp.async.wait_group 1;" ::: "memory");
            __syncthreads();
            LOAD_STAGE_BIG(i + 2, (i + 2) % STAGES);
        } else {
            asm volatile("cp.async.wait_group 0;" ::: "memory");
            __syncthreads();
        }
        const uint32_t sA = sb + st * BIG_STG;
        const uint32_t sB = sb + STAGES * BIG_STG + st * BIG_STG;
#pragma unroll
        for (int ks = 0; ks < 4; ks++) {     // 4 x k16 per BK=64 chunk
            uint32_t a[4][4], b[4][4];
#pragma unroll
            for (int nh = 0; nh < 4; nh++)
                ldsm4(b[nh], sB + SWZ(b_base[nh] + (uint32_t)(ks * 32)));
#pragma unroll
            for (int mt = 0; mt < 4; mt++)
                ldsm4(a[mt], sA + SWZ(a_base[mt] + (uint32_t)(ks * 32)));
#pragma unroll
            for (int mt = 0; mt < 4; mt++)
#pragma unroll
                for (int nt = 0; nt < 8; nt++)
                    mma_f16(acc[mt][nt], a[mt], b[nt >> 1][nt & 1], b[nt >> 1][(nt & 1) + 2]);
        }
    }
#undef LOAD_STAGE_BIG

    const int mrow = lane >> 2;
    const int mcol = (lane & 3) << 1;
#pragma unroll
    for (int mt = 0; mt < 4; mt++) {
#pragma unroll
        for (int nt = 0; nt < 8; nt++) {
            int row = m0 + warp_m * 64 + mt * 16 + mrow;
            int col = n0 + warp_n * 64 + nt * 8 + mcol;
            *(__half2*)&C[(size_t)row * ldc + col] =
                __floats2half2_rn(acc[mt][nt][0], acc[mt][nt][1]);
            *(__half2*)&C[(size_t)(row + 8) * ldc + col] =
                __floats2half2_rn(acc[mt][nt][2], acc[mt][nt][3]);
        }
    }
}

// ---------------------------------------------------------------------------
// FUSED: small GEMM (blocks 0..127) + transpose_x (blocks 128..3199).
// ---------------------------------------------------------------------------
#define SML_ASTG 8192
#define SML_BSTG 16384
#define SML_SMEM (STAGES * (SML_ASTG + SML_BSTG))   // 73728
#define SML_BLOCKS 128
#define TX_BLOCKS (6 * 32 * 16)                      // 3072

__global__ void __launch_bounds__(256) fused_sg_tx(const __half* __restrict__ Asg,
                                                   const __half* __restrict__ Bsg,
                                                   __half* __restrict__ Csg,
                                                   const float* __restrict__ x) {
    extern __shared__ char smem[];
    const int tid = threadIdx.x;

    if (blockIdx.x < SML_BLOCKS) {
        const int K = NF_, ldc = NF_;
        const uint32_t sb = smem_u32(smem);
        const int lane = tid & 31, wid = tid >> 5;
        const int bx = blockIdx.x & 7, by = blockIdx.x >> 3;
        const int m0 = by * 64, n0 = bx * 128;
        const int warp_m = wid & 1, warp_n = wid >> 1;

        const int r = tid >> 3;
        const int o16 = (tid & 7) << 4;
        const int c8 = (tid & 7) << 3;

        float acc[2][4][4];
#pragma unroll
        for (int i = 0; i < 2; i++)
#pragma unroll
            for (int j = 0; j < 4; j++)
#pragma unroll
                for (int k = 0; k < 4; k++) acc[i][j][k] = 0.f;

        const int lrow = lane & 15;
        const int lcol = (lane >> 4) << 4;
        uint32_t a_base[2], b_base[2];
#pragma unroll
        for (int mt = 0; mt < 2; mt++)
            a_base[mt] = (uint32_t)((warp_m * 32 + mt * 16 + lrow) * 128 + lcol);
#pragma unroll
        for (int nh = 0; nh < 2; nh++)
            b_base[nh] = (uint32_t)((warp_n * 32 + nh * 16 + lrow) * 128 + lcol);

#define LOAD_STAGE_SML(chunk, stage)                                               \
    do {                                                                           \
        uint32_t sA = sb + (stage) * SML_ASTG;                                     \
        uint32_t sB = sb + STAGES * SML_ASTG + (stage) * SML_BSTG;                 \
        int k0 = (chunk) * BK;                                                     \
        _Pragma("unroll") for (int t = 0; t < 2; t++) {                            \
            int rr = r + t * 32;                                                   \
            cp16(sA + SWZ((uint32_t)(rr * 128 + o16)),                             \
                 Asg + (size_t)(m0 + rr) * K + k0 + c8);                           \
        }                                                                          \
        _Pragma("unroll") for (int t = 0; t < 4; t++) {                            \
            int rr = r + t * 32;                                                   \
            cp16(sB + SWZ((uint32_t)(rr * 128 + o16)),                             \
                 Bsg + (size_t)(n0 + rr) * K + k0 + c8);                           \
        }                                                                          \
        CP_COMMIT();                                                               \
    } while (0)

        LOAD_STAGE_SML(0, 0);
        LOAD_STAGE_SML(1, 1);

        const int nk = K / BK;  // 16
        for (int i = 0; i < nk; i++) {
            const int st = i % STAGES;
            if (i + 2 < nk) {
                asm volatile("cp.async.wait_group 1;" ::: "memory");
                __syncthreads();
                LOAD_STAGE_SML(i + 2, (i + 2) % STAGES);
            } else {
                asm volatile("cp.async.wait_group 0;" ::: "memory");
                __syncthreads();
            }
            const uint32_t sA = sb + st * SML_ASTG;
            const uint32_t sB = sb + STAGES * SML_ASTG + st * SML_BSTG;
#pragma unroll
            for (int ks = 0; ks < 4; ks++) {
                uint32_t a[2][4], b[2][4];
#pragma unroll
                for (int nh = 0; nh < 2; nh++)
                    ldsm4(b[nh], sB + SWZ(b_base[nh] + (uint32_t)(ks * 32)));
#pragma unroll
                for (int mt = 0; mt < 2; mt++)
                    ldsm4(a[mt], sA + SWZ(a_base[mt] + (uint32_t)(ks * 32)));
#pragma unroll
                for (int mt = 0; mt < 2; mt++)
#pragma unroll
                    for (int nt = 0; nt < 4; nt++)
                        mma_f16(acc[mt][nt], a[mt], b[nt >> 1][nt & 1], b[nt >> 1][(nt & 1) + 2]);
            }
        }
#undef LOAD_STAGE_SML

        const int mrow = lane >> 2;
        const int mcol = (lane & 3) << 1;
#pragma unroll
        for (int mt = 0; mt < 2; mt++) {
#pragma unroll
            for (int nt = 0; nt < 4; nt++) {
                int row = m0 + warp_m * 32 + mt * 16 + mrow;
                int col = n0 + warp_n * 32 + nt * 8 + mcol;
                *(__half2*)&Csg[(size_t)row * ldc + col] =
                    __floats2half2_rn(acc[mt][nt][0], acc[mt][nt][1]);
                *(__half2*)&Csg[(size_t)(row + 8) * ldc + col] =
                    __floats2half2_rn(acc[mt][nt][2], acc[mt][nt][3]);
            }
        }
    } else {
        float (*tile)[33] = (float(*)[33])smem;
        const int bb = blockIdx.x - SML_BLOCKS;
        const int bxx = bb % 6;
        const int byy = (bb / 6) & 31;
        const int bz = bb / (6 * 32);
        const int c0 = byy * 32;
        const int tn0 = bxx * 128;
        const int lane = tid & 31, wid = tid >> 5;

#pragma unroll
        for (int p = 0; p < 4; p++) {
            const int c = wid + p * 8;
            float4 v = *(const float4*)(x + ((size_t)bz * C_ + c0 + c) * TN_ + tn0 + lane * 4);
            tile[lane * 4 + 0][c] = v.x;
            tile[lane * 4 + 1][c] = v.y;
            tile[lane * 4 + 2][c] = v.z;
            tile[lane * 4 + 3][c] = v.w;
        }
        __syncthreads();

        const int cc = (lane & 7) * 4;
        const int tnw = wid * 4 + (lane >> 3);
#pragma unroll
        for (int p = 0; p < 4; p++) {
            const int tn = tnw + p * 32;
            __half2 h01 = __floats2half2_rn(tile[tn][cc + 0], tile[tn][cc + 1]);
            __half2 h23 = __floats2half2_rn(tile[tn][cc + 2], tile[tn][cc + 3]);
            uint2 st;
            st.x = *(uint32_t*)&h01;
            st.y = *(uint32_t*)&h23;
            *(uint2*)(g_feat + ((size_t)bz * TN_ + tn0 + tn) * NF_ + c0 + cc) = st;
        }
    }
}

// ---------------------------------------------------------------------------
// Fused prep: blocks 0-2047 round wt/wp -> half; 2048-3071 transpose wg -> half;
// 3072-3199 bias cross-term vectors (fp32 exact).
// ---------------------------------------------------------------------------
__global__ void prep_w(const float* __restrict__ wt, const float* __restrict__ wp,
                       const float* __restrict__ wg,
                       const float* __restrict__ bt, const float* __restrict__ bp) {
    const int bi = blockIdx.x;
    const int tid = threadIdx.x;
    if (bi < 2048) {
        const float4* in = (bi < 1024) ? (const float4*)wt : (const float4*)wp;
        __half* outp = (bi < 1024) ? g_wtr : g_wpr;
        const int i = (bi & 1023) * 256 + tid;
        float4 v = in[i];
        __half2 h01 = __floats2half2_rn(v.x, v.y);
        __half2 h23 = __floats2half2_rn(v.z, v.w);
        uint2 st;
        st.x = *(uint32_t*)&h01;
        st.y = *(uint32_t*)&h23;
        *(uint2*)(outp + (size_t)i * 4) = st;
    } else if (bi < 3072) {
        __shared__ float tile[32][33];
        const int bb = bi - 2048;
        const int k0 = (bb >> 5) * 32;
        const int n0 = (bb & 31) * 32;
        const int tx = tid & 31, ty = tid >> 5;
#pragma unroll
        for (int i = 0; i < 32; i += 8)
            tile[ty + i][tx] = wg[(size_t)(k0 + ty + i) * NF_ + n0 + tx];
        __syncthreads();
        __half* dst = g_BigB + (size_t)NF_ * NF_;
#pragma unroll
        for (int i = 0; i < 32; i += 8)
            dst[(size_t)(n0 + ty + i) * NF_ + k0 + tx] = __float2half_rn(tile[tx][ty + i]);
    } else {
        const int lane = tid & 31, warp = tid >> 5;
        const int c = (bi - 3072) * 8 + warp;
        const float* wtr = wt + (size_t)c * NF_;
        const float* wpr = wp + (size_t)c * NF_;
        float a = 0.f, b2 = 0.f;
#pragma unroll
        for (int i = 0; i < 32; i++) {
            const int k = lane + 32 * i;
            a  += wtr[k] * bp[k];
            b2 += wpr[k] * bt[k];
        }
#pragma unroll
        for (int o = 16; o > 0; o >>= 1) {
            a  += __shfl_xor_sync(0xffffffffu, a, o);
            b2 += __shfl_xor_sync(0xffffffffu, b2, o);
        }
        if (lane == 0) { g_vtp[c] = a; g_vpt[c] = b2; }
        if (bi == 3072 && warp == 0) {
            float s = 0.f;
#pragma unroll
            for (int i = 0; i < 32; i++) {
                const int k = lane + 32 * i;
                s += bt[k] * bp[k];
            }
#pragma unroll
            for (int o = 16; o > 0; o >>= 1) s += __shfl_xor_sync(0xffffffffu, s, o);
            if (lane == 0) g_bb[0] = s;
        }
    }
}

// ---------------------------------------------------------------------------
// Kernel A: per-frame logits + mask + softmax -> g_rg (+rg_out). 384 threads.
// ---------------------------------------------------------------------------
__global__ void __launch_bounds__(384) rg_kernel(const float* __restrict__ Abox,
                                                 float* __restrict__ rg_out) {
    extern __shared__ char smraw[];
    __half* sfm = (__half*)smraw;    // [12][1024] fp16 feat (24KB)
    const int f = blockIdx.x;
    const int tid = threadIdx.x;
    const int lane = tid & 31, warp = tid >> 5;   // 12 warps

    __shared__ float px[12], py[12], sqs[12];
    __shared__ float s_u[12], s_v[12];

    if (tid < 12) {
        const float* bx = Abox + ((size_t)f * 12 + tid) * 4;
        float cx = (bx[0] + bx[2]) * 0.5f;
        float cy = (bx[1] + bx[3]) * 0.5f;
        px[tid] = cx; py[tid] = cy; sqs[tid] = cx * cx + cy * cy;
    }

    // stage feat_f: 6144 uint32 / 384 threads = 16 iters
    {
        const uint32_t* src = (const uint32_t*)(g_feat + (size_t)f * 12 * NF_);
        uint32_t* dst = (uint32_t*)sfm;
#pragma unroll
        for (int i = 0; i < 16; i++)
            dst[tid + i * 384] = src[tid + i * 384];
    }
    __syncthreads();

    // phase 1: bias cross terms
    {
        const __half2* frow = (const __half2*)(sfm + warp * NF_);
        const float2* vt2 = (const float2*)g_vtp;
        const float2* vp2 = (const float2*)g_vpt;
        float ua = 0.f, va = 0.f;
#pragma unroll
        for (int k = 0; k < 16; k++) {
            float2 fv = __half22float2(frow[lane + 32 * k]);
            float2 t = vt2[lane + 32 * k];
            float2 p = vp2[lane + 32 * k];
            ua += fv.x * t.x + fv.y * t.y;
            va += fv.x * p.x + fv.y * p.y;
        }
#pragma unroll
        for (int o = 16; o > 0; o >>= 1) {
            ua += __shfl_xor_sync(0xffffffffu, ua, o);
            va += __shfl_xor_sync(0xffffffffu, va, o);
        }
        if (lane == 0) { s_u[warp] = ua; s_v[warp] = va; }
    }
    __syncthreads();

    // phase 2: logits row n = warp n; mask + softmax; write rg
    {
        const int n = warp;
        const uint2* tM2 = (const uint2*)(g_TG + ((size_t)f * 12 + n) * NB_);
        float4 tr[8];
#pragma unroll
        for (int k = 0; k < 8; k++) {
            uint2 u = tM2[lane + 32 * k];
            float2 f0 = __half22float2(*(__half2*)&u.x);
            float2 f1 = __half22float2(*(__half2*)&u.y);
            tr[k] = make_float4(f0.x, f0.y, f1.x, f1.y);
        }
        float lg[12];
#pragma unroll
        for (int m = 0; m < 12; m++) {
            const uint2* fm2 = (const uint2*)(sfm + m * NF_);
            float a = 0.f;
#pragma unroll
            for (int k = 0; k < 8; k++) {
                uint2 u = fm2[lane + 32 * k];
                float2 f0 = __half22float2(*(__half2*)&u.x);
                float2 f1 = __half22float2(*(__half2*)&u.y);
                a += tr[k].x * f0.x + tr[k].y * f0.y + tr[k].z * f1.x + tr[k].w * f1.y;
            }
#pragma unroll
            for (int o = 16; o > 0; o >>= 1) a += __shfl_xor_sync(0xffffffffu, a, o);
            lg[m] = a;
        }
        if (lane == 0) {
            const float bb = g_bb[0];
            const float scale = 0.03125f;
            float e[12];
            bool msk[12];
            float mx = -INFINITY;
#pragma unroll
            for (int m = 0; m < 12; m++) {
                float d2 = sqs[n] - 2.f * (px[n] * px[m] + py[n] * py[m]) + sqs[m];
                d2 = fmaxf(d2, 0.f);
                float dist = sqrtf(d2);
                msk[m] = (dist > 0.4f);
                float v = (lg[m] + s_u[n] + s_v[m] + bb) * scale;
                e[m] = v;
                if (!msk[m]) mx = fmaxf(mx, v);
            }
            float se = 0.f;
#pragma unroll
            for (int m = 0; m < 12; m++) {
                float ev = msk[m] ? 0.f : expf(e[m] - mx);
                e[m] = ev;
                se += ev;
            }
            float inv = 1.f / se;
#pragma unroll
            for (int m = 0; m < 12; m++) {
                float r = e[m] * inv;
                g_rg[((size_t)f * 12 + n) * 12 + m] = r;
                if (rg_out) rg_out[((size_t)f * 12 + n) * 12 + m] = r;
            }
        }
    }
}

// ---------------------------------------------------------------------------
// Kernel B: agg = rg @ G_f, LayerNorm, ReLU. 512 threads, 3 CTA/SM (low regs:
// loop order m-outer so no gv[] array lives in registers).
// ---------------------------------------------------------------------------
__device__ __forceinline__ float2 blockSum2(float v1, float v2, float* red) {
    const int lane = threadIdx.x & 31, warp = threadIdx.x >> 5;
#pragma unroll
    for (int o = 16; o > 0; o >>= 1) {
        v1 += __shfl_xor_sync(0xffffffffu, v1, o);
        v2 += __shfl_xor_sync(0xffffffffu, v2, o);
    }
    if (lane == 0) { red[warp] = v1; red[warp + 16] = v2; }
    __syncthreads();
    if (threadIdx.x == 0) {
        float s1 = 0.f, s2 = 0.f;
        for (int i = 0; i < 16; i++) { s1 += red[i]; s2 += red[i + 16]; }
        red[32] = s1; red[33] = s2;
    }
    __syncthreads();
    float2 r = make_float2(red[32], red[33]);
    __syncthreads();
    return r;
}

__global__ void __launch_bounds__(512, 3) agg_ln_kernel(const float* __restrict__ ln_w,
                                                        const float* __restrict__ ln_b,
                                                        float* __restrict__ out) {
    const int f = blockIdx.x;
    const int tid = threadIdx.x;

    __shared__ float s_rg[144];
    __shared__ float red[34];

    if (tid < 144) s_rg[tid] = g_rg[(size_t)f * 144 + tid];
    __syncthreads();

    // agg accumulation, m-outer (no gv array)
    float ax[12], ay[12];
#pragma unroll
    for (int n = 0; n < 12; n++) { ax[n] = 0.f; ay[n] = 0.f; }
#pragma unroll
    for (int m = 0; m < 12; m++) {
        const __half2* g2 = (const __half2*)(g_TG + ((size_t)f * 12 + m) * NB_ + NF_);
        float2 g = __half22float2(g2[tid]);
#pragma unroll
        for (int n = 0; n < 12; n++) {
            float w = s_rg[n * 12 + m];
            ax[n] += w * g.x;
            ay[n] += w * g.y;
        }
    }
    float lsum = 0.f, lsq = 0.f;
#pragma unroll
    for (int n = 0; n < 12; n++) {
        lsum += ax[n] + ay[n];
        lsq += ax[n] * ax[n] + ay[n] * ay[n];
    }
    float2 mom = blockSum2(lsum, lsq, red);
    const float mu = mom.x * (1.f / 12288.f);
    const float var = mom.y * (1.f / 12288.f) - mu * mu;
    const float rstd = rsqrtf(var + 1e-5f);

    const float2* lw2 = (const float2*)ln_w;
    const float2* lb2 = (const float2*)ln_b;
    float2* out2 = (float2*)out;
#pragma unroll
    for (int n = 0; n < 12; n++) {
        float2 w = lw2[n * 512 + tid];
        float2 b = lb2[n * 512 + tid];
        float yx = (ax[n] - mu) * rstd * w.x + b.x;
        float yy = (ay[n] - mu) * rstd * w.y + b.y;
        out2[((size_t)f * 12 + n) * 512 + tid] = make_float2(fmaxf(yx, 0.f), fmaxf(yy, 0.f));
    }
}

// ---------------------------------------------------------------------------
extern "C" void kernel_launch(void* const* d_in, const int* in_sizes, int n_in,
                              void* d_out, int out_size) {
    const float* x  = (const float*)d_in[0];
    const float* A  = (const float*)d_in[1];
    const float* wt = (const float*)d_in[2];
    const float* bt = (const float*)d_in[3];
    const float* wp = (const float*)d_in[4];
    const float* bp = (const float*)d_in[5];
    const float* wg = (const float*)d_in[6];
    const float* lw = (const float*)d_in[7];
    const float* lb = (const float*)d_in[8];

    float* out = (float*)d_out;
    float* rg = (out_size >= (int)(ROWS_ * NF_ + BT_ * N_ * N_))
                    ? out + (size_t)ROWS_ * NF_
                    : nullptr;

    __half *feat, *TG, *BigB, *wtr, *wpr;
    cudaGetSymbolAddress((void**)&feat, g_feat);
    cudaGetSymbolAddress((void**)&TG, g_TG);
    cudaGetSymbolAddress((void**)&BigB, g_BigB);
    cudaGetSymbolAddress((void**)&wtr, g_wtr);
    cudaGetSymbolAddress((void**)&wpr, g_wpr);

    cudaFuncSetAttribute(fused_sg_tx,
                         cudaFuncAttributeMaxDynamicSharedMemorySize, SML_SMEM);
    cudaFuncSetAttribute(mma_gemm_big,
                         cudaFuncAttributeMaxDynamicSharedMemorySize, BIG_SMEM);
    cudaFuncSetAttribute(rg_kernel,
                         cudaFuncAttributeMaxDynamicSharedMemorySize, 24576);

    // 5 launches: prep -> [small GEMM + transpose] -> big GEMM -> rg -> agg+LN
    prep_w<<<3200, 256>>>(wt, wp, wg, bt, bp);                               // 1
    fused_sg_tx<<<SML_BLOCKS + TX_BLOCKS, 256, SML_SMEM>>>(                  // 2
        wpr, wtr, BigB, x);
    mma_gemm_big<<<dim3(NB_ / 128, ROWS_ / 128), 128, BIG_SMEM>>>(           // 3
        feat, BigB, TG);
    rg_kernel<<<BT_, 384, 24576>>>(A, rg);                                   // 4
    agg_ln_kernel<<<BT_, 512>>>(lw, lb, out);                                // 5
}

// round 15
// speedup vs baseline: 1.0194x; 1.0194x over previous
#include <cuda_runtime.h>
#include <cuda_fp16.h>
#include <math.h>
#include <stdint.h>

// Problem constants
#define B_    16
#define C_    1024
#define T_    64
#define N_    12
#define BT_   (B_ * T_)       // 1024 frames
#define NF_   1024
#define ROWS_ (BT_ * N_)      // 12288
#define TN_   (T_ * N_)       // 768
#define NB_   2048            // fused B rows: [MwT | wg^T]

// Scratch (static device globals)
__device__ __half g_feat[ROWS_ * NF_];   // feat, rn-rounded to fp16
__device__ __half g_TG[ROWS_ * NB_];     // [tM | G] fused output (fp16)
__device__ __half g_BigB[NB_ * NF_];     // rows 0-1023: MwT, 1024-2047: wg^T
__device__ __half g_wtr[NF_ * NF_];      // Wtheta rounded to fp16
__device__ __half g_wpr[NF_ * NF_];      // Wphi rounded to fp16
__device__ float  g_vtp[NF_];
__device__ float  g_vpt[NF_];
__device__ float  g_bb[1];

// ---------------------------------------------------------------------------
// Helpers (baseline PTX only)
// ---------------------------------------------------------------------------
__device__ __forceinline__ uint32_t smem_u32(const void* p) {
    uint32_t a;
    asm("{ .reg .u64 t; cvta.to.shared.u64 t, %1; cvt.u32.u64 %0, t; }" : "=r"(a) : "l"(p));
    return a;
}
__device__ __forceinline__ void cp16(uint32_t s, const void* g) {
    asm volatile("cp.async.cg.shared.global [%0], [%1], 16;" :: "r"(s), "l"(g) : "memory");
}
#define CP_COMMIT() asm volatile("cp.async.commit_group;" ::: "memory")
#define SWZ(x) ((x) ^ (((x) >> 3) & 0x70))

__device__ __forceinline__ void ldsm4(uint32_t* r, uint32_t addr) {
    asm volatile("ldmatrix.sync.aligned.m8n8.x4.shared.b16 {%0,%1,%2,%3}, [%4];"
                 : "=r"(r[0]), "=r"(r[1]), "=r"(r[2]), "=r"(r[3]) : "r"(addr));
}
// fp16 MMA, fp32 accumulate
__device__ __forceinline__ void mma_f16(float* c, const uint32_t* a, uint32_t b0, uint32_t b1) {
    asm volatile("mma.sync.aligned.m16n8k16.row.col.f32.f16.f16.f32 "
                 "{%0,%1,%2,%3}, {%4,%5,%6,%7}, {%8,%9}, {%0,%1,%2,%3};"
                 : "+f"(c[0]), "+f"(c[1]), "+f"(c[2]), "+f"(c[3])
                 : "r"(a[0]), "r"(a[1]), "r"(a[2]), "r"(a[3]), "r"(b0), "r"(b1));
}

#define BK 64          // fp16: 64 halves = 128B rows
#define STAGES 3

// ---------------------------------------------------------------------------
// Big GEMM (fp16): 128 thr (4 warps), CTA 128x128, warp 64x64, 3 stages,
// 2 CTA/SM. C[m,n] = sum_k A[m,k]*Bm[n,k]; half in, half out.
// ---------------------------------------------------------------------------
#define BIG_STG 16384
#define BIG_SMEM (STAGES * 2 * BIG_STG)   // 98304

__global__ void __launch_bounds__(128, 2) mma_gemm_big(const __half* __restrict__ A,
                                                       const __half* __restrict__ Bm,
                                                       __half* __restrict__ C) {
    const int K = NF_, ldc = NB_;
    extern __shared__ char smem[];
    const uint32_t sb = smem_u32(smem);
    const int tid = threadIdx.x, lane = tid & 31, wid = tid >> 5;
    const int m0 = blockIdx.y * 128, n0 = blockIdx.x * 128;
    const int warp_m = wid & 1, warp_n = wid >> 1;   // 2x2 warps, 64x64 each

    const int r = tid >> 3;
    const int o16 = (tid & 7) << 4;
    const int c8 = (tid & 7) << 3;

    float acc[4][8][4];
#pragma unroll
    for (int i = 0; i < 4; i++)
#pragma unroll
        for (int j = 0; j < 8; j++)
#pragma unroll
            for (int k = 0; k < 4; k++) acc[i][j][k] = 0.f;

    const int lrow = lane & 15;
    const int lcol = (lane >> 4) << 4;
    uint32_t a_base[4], b_base[4];
#pragma unroll
    for (int mt = 0; mt < 4; mt++)
        a_base[mt] = (uint32_t)((warp_m * 64 + mt * 16 + lrow) * 128 + lcol);
#pragma unroll
    for (int nh = 0; nh < 4; nh++)
        b_base[nh] = (uint32_t)((warp_n * 64 + nh * 16 + lrow) * 128 + lcol);

#define LOAD_STAGE_BIG(chunk, stage)                                               \
    do {                                                                           \
        uint32_t sA = sb + (stage) * BIG_STG;                                      \
        uint32_t sB = sb + STAGES * BIG_STG + (stage) * BIG_STG;                   \
        int k0 = (chunk) * BK;                                                     \
        _Pragma("unroll") for (int t = 0; t < 8; t++) {                            \
            int rr = r + t * 16;                                                   \
            cp16(sA + SWZ((uint32_t)(rr * 128 + o16)),                             \
                 A + (size_t)(m0 + rr) * K + k0 + c8);                             \
        }                                                                          \
        _Pragma("unroll") for (int t = 0; t < 8; t++) {                            \
            int rr = r + t * 16;                                                   \
            cp16(sB + SWZ((uint32_t)(rr * 128 + o16)),                             \
                 Bm + (size_t)(n0 + rr) * K + k0 + c8);                            \
        }                                                                          \
        CP_COMMIT();                                                               \
    } while (0)

    LOAD_STAGE_BIG(0, 0);
    LOAD_STAGE_BIG(1, 1);

    const int nk = K / BK;  // 16
    for (int i = 0; i < nk; i++) {
        const int st = i % STAGES;
        if (i + 2 < nk) {
            asm volatile("cp.async.wait_group 1;" ::: "memory");
            __syncthreads();
            LOAD_STAGE_BIG(i + 2, (i + 2) % STAGES);
        } else {
            asm volatile("cp.async.wait_group 0;" ::: "memory");
            __syncthreads();
        }
        const uint32_t sA = sb + st * BIG_STG;
        const uint32_t sB = sb + STAGES * BIG_STG + st * BIG_STG;
#pragma unroll
        for (int ks = 0; ks < 4; ks++) {     // 4 x k16 per BK=64 chunk
            uint32_t a[4][4], b[4][4];
#pragma unroll
            for (int nh = 0; nh < 4; nh++)
                ldsm4(b[nh], sB + SWZ(b_base[nh] + (uint32_t)(ks * 32)));
#pragma unroll
            for (int mt = 0; mt < 4; mt++)
                ldsm4(a[mt], sA + SWZ(a_base[mt] + (uint32_t)(ks * 32)));
#pragma unroll
            for (int mt = 0; mt < 4; mt++)
#pragma unroll
                for (int nt = 0; nt < 8; nt++)
                    mma_f16(acc[mt][nt], a[mt], b[nt >> 1][nt & 1], b[nt >> 1][(nt & 1) + 2]);
        }
    }
#undef LOAD_STAGE_BIG

    const int mrow = lane >> 2;
    const int mcol = (lane & 3) << 1;
#pragma unroll
    for (int mt = 0; mt < 4; mt++) {
#pragma unroll
        for (int nt = 0; nt < 8; nt++) {
            int row = m0 + warp_m * 64 + mt * 16 + mrow;
            int col = n0 + warp_n * 64 + nt * 8 + mcol;
            *(__half2*)&C[(size_t)row * ldc + col] =
                __floats2half2_rn(acc[mt][nt][0], acc[mt][nt][1]);
            *(__half2*)&C[(size_t)(row + 8) * ldc + col] =
                __floats2half2_rn(acc[mt][nt][2], acc[mt][nt][3]);
        }
    }
}

// ---------------------------------------------------------------------------
// FUSED: small GEMM (blocks 0..127) + transpose_x (blocks 128..3199).
// ---------------------------------------------------------------------------
#define SML_ASTG 8192
#define SML_BSTG 16384
#define SML_SMEM (STAGES * (SML_ASTG + SML_BSTG))   // 73728
#define SML_BLOCKS 128
#define TX_BLOCKS (6 * 32 * 16)                      // 3072

__global__ void __launch_bounds__(256) fused_sg_tx(const __half* __restrict__ Asg,
                                                   const __half* __restrict__ Bsg,
                                                   __half* __restrict__ Csg,
                                                   const float* __restrict__ x) {
    extern __shared__ char smem[];
    const int tid = threadIdx.x;

    if (blockIdx.x < SML_BLOCKS) {
        const int K = NF_, ldc = NF_;
        const uint32_t sb = smem_u32(smem);
        const int lane = tid & 31, wid = tid >> 5;
        const int bx = blockIdx.x & 7, by = blockIdx.x >> 3;
        const int m0 = by * 64, n0 = bx * 128;
        const int warp_m = wid & 1, warp_n = wid >> 1;

        const int r = tid >> 3;
        const int o16 = (tid & 7) << 4;
        const int c8 = (tid & 7) << 3;

        float acc[2][4][4];
#pragma unroll
        for (int i = 0; i < 2; i++)
#pragma unroll
            for (int j = 0; j < 4; j++)
#pragma unroll
                for (int k = 0; k < 4; k++) acc[i][j][k] = 0.f;

        const int lrow = lane & 15;
        const int lcol = (lane >> 4) << 4;
        uint32_t a_base[2], b_base[2];
#pragma unroll
        for (int mt = 0; mt < 2; mt++)
            a_base[mt] = (uint32_t)((warp_m * 32 + mt * 16 + lrow) * 128 + lcol);
#pragma unroll
        for (int nh = 0; nh < 2; nh++)
            b_base[nh] = (uint32_t)((warp_n * 32 + nh * 16 + lrow) * 128 + lcol);

#define LOAD_STAGE_SML(chunk, stage)                                               \
    do {                                                                           \
        uint32_t sA = sb + (stage) * SML_ASTG;                                     \
        uint32_t sB = sb + STAGES * SML_ASTG + (stage) * SML_BSTG;                 \
        int k0 = (chunk) * BK;                                                     \
        _Pragma("unroll") for (int t = 0; t < 2; t++) {                            \
            int rr = r + t * 32;                                                   \
            cp16(sA + SWZ((uint32_t)(rr * 128 + o16)),                             \
                 Asg + (size_t)(m0 + rr) * K + k0 + c8);                           \
        }                                                                          \
        _Pragma("unroll") for (int t = 0; t < 4; t++) {                            \
            int rr = r + t * 32;                                                   \
            cp16(sB + SWZ((uint32_t)(rr * 128 + o16)),                             \
                 Bsg + (size_t)(n0 + rr) * K + k0 + c8);                           \
        }                                                                          \
        CP_COMMIT();                                                               \
    } while (0)

        LOAD_STAGE_SML(0, 0);
        LOAD_STAGE_SML(1, 1);

        const int nk = K / BK;  // 16
        for (int i = 0; i < nk; i++) {
            const int st = i % STAGES;
            if (i + 2 < nk) {
                asm volatile("cp.async.wait_group 1;" ::: "memory");
                __syncthreads();
                LOAD_STAGE_SML(i + 2, (i + 2) % STAGES);
            } else {
                asm volatile("cp.async.wait_group 0;" ::: "memory");
                __syncthreads();
            }
            const uint32_t sA = sb + st * SML_ASTG;
            const uint32_t sB = sb + STAGES * SML_ASTG + st * SML_BSTG;
#pragma unroll
            for (int ks = 0; ks < 4; ks++) {
                uint32_t a[2][4], b[2][4];
#pragma unroll
                for (int nh = 0; nh < 2; nh++)
                    ldsm4(b[nh], sB + SWZ(b_base[nh] + (uint32_t)(ks * 32)));
#pragma unroll
                for (int mt = 0; mt < 2; mt++)
                    ldsm4(a[mt], sA + SWZ(a_base[mt] + (uint32_t)(ks * 32)));
#pragma unroll
                for (int mt = 0; mt < 2; mt++)
#pragma unroll
                    for (int nt = 0; nt < 4; nt++)
                        mma_f16(acc[mt][nt], a[mt], b[nt >> 1][nt & 1], b[nt >> 1][(nt & 1) + 2]);
            }
        }
#undef LOAD_STAGE_SML

        const int mrow = lane >> 2;
        const int mcol = (lane & 3) << 1;
#pragma unroll
        for (int mt = 0; mt < 2; mt++) {
#pragma unroll
            for (int nt = 0; nt < 4; nt++) {
                int row = m0 + warp_m * 32 + mt * 16 + mrow;
                int col = n0 + warp_n * 32 + nt * 8 + mcol;
                *(__half2*)&Csg[(size_t)row * ldc + col] =
                    __floats2half2_rn(acc[mt][nt][0], acc[mt][nt][1]);
                *(__half2*)&Csg[(size_t)(row + 8) * ldc + col] =
                    __floats2half2_rn(acc[mt][nt][2], acc[mt][nt][3]);
            }
        }
    } else {
        float (*tile)[33] = (float(*)[33])smem;
        const int bb = blockIdx.x - SML_BLOCKS;
        const int bxx = bb % 6;
        const int byy = (bb / 6) & 31;
        const int bz = bb / (6 * 32);
        const int c0 = byy * 32;
        const int tn0 = bxx * 128;
        const int lane = tid & 31, wid = tid >> 5;

#pragma unroll
        for (int p = 0; p < 4; p++) {
            const int c = wid + p * 8;
            float4 v = *(const float4*)(x + ((size_t)bz * C_ + c0 + c) * TN_ + tn0 + lane * 4);
            tile[lane * 4 + 0][c] = v.x;
            tile[lane * 4 + 1][c] = v.y;
            tile[lane * 4 + 2][c] = v.z;
            tile[lane * 4 + 3][c] = v.w;
        }
        __syncthreads();

        const int cc = (lane & 7) * 4;
        const int tnw = wid * 4 + (lane >> 3);
#pragma unroll
        for (int p = 0; p < 4; p++) {
            const int tn = tnw + p * 32;
            __half2 h01 = __floats2half2_rn(tile[tn][cc + 0], tile[tn][cc + 1]);
            __half2 h23 = __floats2half2_rn(tile[tn][cc + 2], tile[tn][cc + 3]);
            uint2 st;
            st.x = *(uint32_t*)&h01;
            st.y = *(uint32_t*)&h23;
            *(uint2*)(g_feat + ((size_t)bz * TN_ + tn0 + tn) * NF_ + c0 + cc) = st;
        }
    }
}

// ---------------------------------------------------------------------------
// Fused prep: blocks 0-2047 round wt/wp -> half; 2048-3071 transpose wg -> half;
// 3072-3199 bias cross-term vectors (fp32 exact).
// ---------------------------------------------------------------------------
__global__ void prep_w(const float* __restrict__ wt, const float* __restrict__ wp,
                       const float* __restrict__ wg,
                       const float* __restrict__ bt, const float* __restrict__ bp) {
    const int bi = blockIdx.x;
    const int tid = threadIdx.x;
    if (bi < 2048) {
        const float4* in = (bi < 1024) ? (const float4*)wt : (const float4*)wp;
        __half* outp = (bi < 1024) ? g_wtr : g_wpr;
        const int i = (bi & 1023) * 256 + tid;
        float4 v = in[i];
        __half2 h01 = __floats2half2_rn(v.x, v.y);
        __half2 h23 = __floats2half2_rn(v.z, v.w);
        uint2 st;
        st.x = *(uint32_t*)&h01;
        st.y = *(uint32_t*)&h23;
        *(uint2*)(outp + (size_t)i * 4) = st;
    } else if (bi < 3072) {
        __shared__ float tile[32][33];
        const int bb = bi - 2048;
        const int k0 = (bb >> 5) * 32;
        const int n0 = (bb & 31) * 32;
        const int tx = tid & 31, ty = tid >> 5;
#pragma unroll
        for (int i = 0; i < 32; i += 8)
            tile[ty + i][tx] = wg[(size_t)(k0 + ty + i) * NF_ + n0 + tx];
        __syncthreads();
        __half* dst = g_BigB + (size_t)NF_ * NF_;
#pragma unroll
        for (int i = 0; i < 32; i += 8)
            dst[(size_t)(n0 + ty + i) * NF_ + k0 + tx] = __float2half_rn(tile[tx][ty + i]);
    } else {
        const int lane = tid & 31, warp = tid >> 5;
        const int c = (bi - 3072) * 8 + warp;
        const float* wtr = wt + (size_t)c * NF_;
        const float* wpr = wp + (size_t)c * NF_;
        float a = 0.f, b2 = 0.f;
#pragma unroll
        for (int i = 0; i < 32; i++) {
            const int k = lane + 32 * i;
            a  += wtr[k] * bp[k];
            b2 += wpr[k] * bt[k];
        }
#pragma unroll
        for (int o = 16; o > 0; o >>= 1) {
            a  += __shfl_xor_sync(0xffffffffu, a, o);
            b2 += __shfl_xor_sync(0xffffffffu, b2, o);
        }
        if (lane == 0) { g_vtp[c] = a; g_vpt[c] = b2; }
        if (bi == 3072 && warp == 0) {
            float s = 0.f;
#pragma unroll
            for (int i = 0; i < 32; i++) {
                const int k = lane + 32 * i;
                s += bt[k] * bp[k];
            }
#pragma unroll
            for (int o = 16; o > 0; o >>= 1) s += __shfl_xor_sync(0xffffffffu, s, o);
            if (lane == 0) g_bb[0] = s;
        }
    }
}

// ---------------------------------------------------------------------------
// Combined block reduction of two values (one smem round).
// ---------------------------------------------------------------------------
__device__ __forceinline__ float2 blockSum2(float v1, float v2, float* red) {
    const int lane = threadIdx.x & 31, warp = threadIdx.x >> 5;
#pragma unroll
    for (int o = 16; o > 0; o >>= 1) {
        v1 += __shfl_xor_sync(0xffffffffu, v1, o);
        v2 += __shfl_xor_sync(0xffffffffu, v2, o);
    }
    if (lane == 0) { red[warp] = v1; red[warp + 16] = v2; }
    __syncthreads();
    if (threadIdx.x == 0) {
        float s1 = 0.f, s2 = 0.f;
        for (int i = 0; i < 16; i++) { s1 += red[i]; s2 += red[i + 16]; }
        red[32] = s1; red[33] = s2;
    }
    __syncthreads();
    float2 r = make_float2(red[32], red[33]);
    __syncthreads();
    return r;
}

__device__ __forceinline__ float2 h2f(uint32_t u) {
    return __half22float2(*(__half2*)&u);
}

// Per-frame: logits, mask, softmax, agg, LN, ReLU. feat staged in smem (fp16),
// uint4 smem reads in phase 2, m-outer phase 3. 64-reg cap -> 2 CTA/SM.
__global__ void __launch_bounds__(512, 2) frame_kernel(const float* __restrict__ Abox,
                                                       const float* __restrict__ ln_w,
                                                       const float* __restrict__ ln_b,
                                                       float* __restrict__ out,
                                                       float* __restrict__ rg_out) {
    extern __shared__ char smraw[];
    __half* sfm = (__half*)smraw;    // [12][1024] fp16 feat for this frame (24KB)
    const int f = blockIdx.x;
    const int tid = threadIdx.x;
    const int lane = tid & 31, warp = tid >> 5;

    __shared__ float px[12], py[12], sqs[12];
    __shared__ float s_u[12], s_v[12];
    __shared__ float s_rg[12][12];
    __shared__ float red[34];

    if (tid < 12) {
        const float* bx = Abox + ((size_t)f * 12 + tid) * 4;
        float cx = (bx[0] + bx[2]) * 0.5f;
        float cy = (bx[1] + bx[3]) * 0.5f;
        px[tid] = cx; py[tid] = cy; sqs[tid] = cx * cx + cy * cy;
    }

    // stage feat_f (12 x 1024 halves = 6144 half2) into smem, raw copy
    {
        const uint32_t* src = (const uint32_t*)(g_feat + (size_t)f * 12 * NF_);
        uint32_t* dst = (uint32_t*)sfm;
#pragma unroll
        for (int i = 0; i < 12; i++)
            dst[tid + i * 512] = src[tid + i * 512];
    }
    __syncthreads();

    // phase 1: bias cross terms; feat from smem (half2 -> float)
    if (warp < 12) {
        const __half2* frow = (const __half2*)(sfm + warp * NF_);
        const float2* vt2 = (const float2*)g_vtp;
        const float2* vp2 = (const float2*)g_vpt;
        float ua = 0.f, va = 0.f;
#pragma unroll
        for (int k = 0; k < 16; k++) {
            float2 fv = __half22float2(frow[lane + 32 * k]);
            float2 t = vt2[lane + 32 * k];
            float2 p = vp2[lane + 32 * k];
            ua += fv.x * t.x + fv.y * t.y;
            va += fv.x * p.x + fv.y * p.y;
        }
#pragma unroll
        for (int o = 16; o > 0; o >>= 1) {
            ua += __shfl_xor_sync(0xffffffffu, ua, o);
            va += __shfl_xor_sync(0xffffffffu, va, o);
        }
        if (lane == 0) { s_u[warp] = ua; s_v[warp] = va; }
    }
    __syncthreads();

    // phase 2: logits; tM (half, uint4 loads) from global, fm (uint4) from smem
    if (warp < 12) {
        const int n = warp;
        const uint4* tM4 = (const uint4*)(g_TG + ((size_t)f * 12 + n) * NB_);
        float4 tr[8];
#pragma unroll
        for (int k = 0; k < 4; k++) {
            uint4 u = tM4[lane + 32 * k];
            float2 a0 = h2f(u.x), a1 = h2f(u.y), a2 = h2f(u.z), a3 = h2f(u.w);
            tr[2 * k]     = make_float4(a0.x, a0.y, a1.x, a1.y);
            tr[2 * k + 1] = make_float4(a2.x, a2.y, a3.x, a3.y);
        }
        float lg[12];
#pragma unroll
        for (int m = 0; m < 12; m++) {
            const uint4* fm4 = (const uint4*)(sfm + m * NF_);
            float a = 0.f;
#pragma unroll
            for (int k = 0; k < 4; k++) {
                uint4 u = fm4[lane + 32 * k];
                float2 b0 = h2f(u.x), b1 = h2f(u.y), b2 = h2f(u.z), b3 = h2f(u.w);
                const float4 t0 = tr[2 * k], t1 = tr[2 * k + 1];
                a += t0.x * b0.x + t0.y * b0.y + t0.z * b1.x + t0.w * b1.y;
                a += t1.x * b2.x + t1.y * b2.y + t1.z * b3.x + t1.w * b3.y;
            }
#pragma unroll
            for (int o = 16; o > 0; o >>= 1) a += __shfl_xor_sync(0xffffffffu, a, o);
            lg[m] = a;
        }
        if (lane == 0) {
            const float bb = g_bb[0];
            const float scale = 0.03125f;
            float e[12];
            bool msk[12];
            float mx = -INFINITY;
#pragma unroll
            for (int m = 0; m < 12; m++) {
                float d2 = sqs[n] - 2.f * (px[n] * px[m] + py[n] * py[m]) + sqs[m];
                d2 = fmaxf(d2, 0.f);
                float dist = sqrtf(d2);
                msk[m] = (dist > 0.4f);
                float v = (lg[m] + s_u[n] + s_v[m] + bb) * scale;
                e[m] = v;
                if (!msk[m]) mx = fmaxf(mx, v);
            }
            float se = 0.f;
#pragma unroll
            for (int m = 0; m < 12; m++) {
                float ev = msk[m] ? 0.f : expf(e[m] - mx);
                e[m] = ev;
                se += ev;
            }
            float inv = 1.f / se;
#pragma unroll
            for (int m = 0; m < 12; m++) {
                float r = e[m] * inv;
                s_rg[n][m] = r;
                if (rg_out) rg_out[((size_t)f * 12 + n) * 12 + m] = r;
            }
        }
    }
    __syncthreads();

    // phase 3: agg = rg @ G_f, m-outer (no gv array); single-pass moments; LN+ReLU
    float ax[12], ay[12];
#pragma unroll
    for (int n = 0; n < 12; n++) { ax[n] = 0.f; ay[n] = 0.f; }
#pragma unroll
    for (int m = 0; m < 12; m++) {
        const __half2* g2 = (const __half2*)(g_TG + ((size_t)f * 12 + m) * NB_ + NF_);
        float2 g = __half22float2(g2[tid]);
#pragma unroll
        for (int n = 0; n < 12; n++) {
            float w = s_rg[n][m];
            ax[n] += w * g.x;
            ay[n] += w * g.y;
        }
    }
    float lsum = 0.f, lsq = 0.f;
#pragma unroll
    for (int n = 0; n < 12; n++) {
        lsum += ax[n] + ay[n];
        lsq += ax[n] * ax[n] + ay[n] * ay[n];
    }
    float2 mom = blockSum2(lsum, lsq, red);
    const float mu = mom.x * (1.f / 12288.f);
    const float var = mom.y * (1.f / 12288.f) - mu * mu;
    const float rstd = rsqrtf(var + 1e-5f);

    const float2* lw2 = (const float2*)ln_w;
    const float2* lb2 = (const float2*)ln_b;
    float2* out2 = (float2*)out;
#pragma unroll
    for (int n = 0; n < 12; n++) {
        float2 w = lw2[n * 512 + tid];
        float2 b = lb2[n * 512 + tid];
        float yx = (ax[n] - mu) * rstd * w.x + b.x;
        float yy = (ay[n] - mu) * rstd * w.y + b.y;
        out2[((size_t)f * 12 + n) * 512 + tid] = make_float2(fmaxf(yx, 0.f), fmaxf(yy, 0.f));
    }
}

// ---------------------------------------------------------------------------
extern "C" void kernel_launch(void* const* d_in, const int* in_sizes, int n_in,
                              void* d_out, int out_size) {
    const float* x  = (const float*)d_in[0];
    const float* A  = (const float*)d_in[1];
    const float* wt = (const float*)d_in[2];
    const float* bt = (const float*)d_in[3];
    const float* wp = (const float*)d_in[4];
    const float* bp = (const float*)d_in[5];
    const float* wg = (const float*)d_in[6];
    const float* lw = (const float*)d_in[7];
    const float* lb = (const float*)d_in[8];

    float* out = (float*)d_out;
    float* rg = (out_size >= (int)(ROWS_ * NF_ + BT_ * N_ * N_))
                    ? out + (size_t)ROWS_ * NF_
                    : nullptr;

    __half *feat, *TG, *BigB, *wtr, *wpr;
    cudaGetSymbolAddress((void**)&feat, g_feat);
    cudaGetSymbolAddress((void**)&TG, g_TG);
    cudaGetSymbolAddress((void**)&BigB, g_BigB);
    cudaGetSymbolAddress((void**)&wtr, g_wtr);
    cudaGetSymbolAddress((void**)&wpr, g_wpr);

    cudaFuncSetAttribute(fused_sg_tx,
                         cudaFuncAttributeMaxDynamicSharedMemorySize, SML_SMEM);
    cudaFuncSetAttribute(mma_gemm_big,
                         cudaFuncAttributeMaxDynamicSharedMemorySize, BIG_SMEM);
    cudaFuncSetAttribute(frame_kernel,
                         cudaFuncAttributeMaxDynamicSharedMemorySize, 24576);

    // 4 launches: prep -> [small GEMM + transpose fused] -> big GEMM -> frame
    prep_w<<<3200, 256>>>(wt, wp, wg, bt, bp);                               // 1
    fused_sg_tx<<<SML_BLOCKS + TX_BLOCKS, 256, SML_SMEM>>>(                  // 2
        wpr, wtr, BigB, x);
    mma_gemm_big<<<dim3(NB_ / 128, ROWS_ / 128), 128, BIG_SMEM>>>(           // 3
        feat, BigB, TG);
    frame_kernel<<<BT_, 512, 24576>>>(A, lw, lb, out, rg);                   // 4
}